// round 2
// baseline (speedup 1.0000x reference)
#include <cuda_runtime.h>

// hybrid_position_embedding: reference ends with softmax over a SINGLETON axis
//   hmap = hybrid[:, None, :]   # (B, 1, N)
//   out  = softmax(hmap, axis=1) == 1.0 exactly (hybrid is finite via int32 cast)
// Output is identically 1.0f for all out_size elements, input-independent.
// (Verified round 1: passed, rel_err = 0.0.)
//
// R1 ncu: fill kernel 3.49us at 25% occ / 6% issue -- launch+wave-tail bound,
// not bandwidth bound (1MB is ~0.1us of L2-write time). Fix: single-wave grid
// (128 CTAs <= 148 SMs), one STG.128 per thread, no second launch.

__global__ void __launch_bounds__(512) fill_ones_exact(float4* __restrict__ out) {
    // exact tiling: no bounds check, no tail
    int i = blockIdx.x * 512 + threadIdx.x;
    out[i] = make_float4(1.0f, 1.0f, 1.0f, 1.0f);
}

__global__ void __launch_bounds__(512) fill_ones_guarded(float* __restrict__ out, int n) {
    int i4 = (blockIdx.x * 512 + threadIdx.x) * 4;
    if (i4 + 3 < n) {
        *reinterpret_cast<float4*>(out + i4) = make_float4(1.0f, 1.0f, 1.0f, 1.0f);
    } else {
        for (int j = i4; j < n; ++j) out[j] = 1.0f;
    }
}

extern "C" void kernel_launch(void* const* d_in, const int* in_sizes, int n_in,
                              void* d_out, int out_size) {
    (void)d_in; (void)in_sizes; (void)n_in;

    const int threads = 512;
    // Fast path: size divides into float4 * threads exactly (true here:
    // 262144 floats = 65536 float4 = 128 blocks * 512 threads).
    if ((out_size & 3) == 0 && ((out_size >> 2) % threads) == 0) {
        int blocks = (out_size >> 2) / threads;   // 128 -> single wave on 148 SMs
        fill_ones_exact<<<blocks, threads>>>((float4*)d_out);
    } else {
        int n_vec4 = (out_size + 3) >> 2;
        int blocks = (n_vec4 + threads - 1) / threads;
        fill_ones_guarded<<<blocks, threads>>>((float*)d_out, out_size);
    }
}

// round 3
// speedup vs baseline: 1.0556x; 1.0556x over previous
#include <cuda_runtime.h>

// hybrid_position_embedding: reference ends with softmax over a SINGLETON axis
//   hmap = hybrid[:, None, :]   # (B, 1, N)
//   out  = softmax(hmap, axis=1) == 1.0 exactly (hybrid is finite via int32 cast)
// Output is identically 1.0f, input-independent. (Verified R1/R2: rel_err = 0.0.)
//
// R2 post-mortem: kernel time is ~3.5-3.7us regardless of grid shape, at 6%
// issue / 0% DRAM -- this is the per-launch overhead floor (T_ovh ~5000 cyc),
// not data movement (1MB ~= 0.1us). Minimize the only remaining variable:
// CTA count. 64 CTAs x 1024 threads x one STG.128 each = exactly 1 MB,
// single wave, minimal distributor work.

__global__ void __launch_bounds__(1024) fill_ones_exact(float4* __restrict__ out) {
    out[blockIdx.x * 1024 + threadIdx.x] = make_float4(1.0f, 1.0f, 1.0f, 1.0f);
}

__global__ void __launch_bounds__(256) fill_ones_guarded(float* __restrict__ out, int n) {
    int i4 = (blockIdx.x * 256 + threadIdx.x) * 4;
    if (i4 + 3 < n) {
        *reinterpret_cast<float4*>(out + i4) = make_float4(1.0f, 1.0f, 1.0f, 1.0f);
    } else {
        for (int j = i4; j < n; ++j) out[j] = 1.0f;
    }
}

extern "C" void kernel_launch(void* const* d_in, const int* in_sizes, int n_in,
                              void* d_out, int out_size) {
    (void)d_in; (void)in_sizes; (void)n_in;

    // Fast path: out_size divides exactly into 1024-thread CTAs of float4
    // stores (true here: 262144 floats = 65536 float4 = 64 CTAs x 1024 thr).
    if ((out_size & 3) == 0 && ((out_size >> 2) & 1023) == 0) {
        int blocks = (out_size >> 2) >> 10;    // 64 -> one CTA on 64 of 148 SMs
        fill_ones_exact<<<blocks, 1024>>>((float4*)d_out);
    } else {
        int n_vec4 = (out_size + 3) >> 2;
        int blocks = (n_vec4 + 255) / 256;
        fill_ones_guarded<<<blocks, 256>>>((float*)d_out, out_size);
    }
}